// round 6
// baseline (speedup 1.0000x reference)
#include <cuda_runtime.h>

#define NTHR  256
#define BT    32
#define H     128
#define G     512
#define T_SEQ 32
#define B_TOT 32768
#define PL    12
#define P_DROP 0.3f
#define DROP_SCALE (1.0f / 0.7f)

#define AROW  132                 // A row stride (words): 128 + 4 pad
#define ASZ   (BT * AROW + 16)    // + slack for the per-bg +4 offset
#define WSZ   (G * 32)            // 512 rows x 32 k-chunk, xor-swizzled granules

struct Smem {
    float At0[ASZ];     // h0 (and decoder h), [b][k] k-contiguous
    float At1[ASZ];     // h1
    float Dt [ASZ];     // dropped layer0 output
    float Ct0[BT * H];  // c state layer0
    float Ct1[BT * H];  // c state layer1 / decoder
    float W  [WSZ];     // staged weight chunk
    float B0 [G], B1 [G], BC [G];
    float Wih0[G * 2], Wihc[G * 2];
    float Wout[2 * H];
    float bout[2];
    float X  [BT * 2];
};

// ---- packed fp32x2 helpers (exact IEEE fma per lane) ----
__device__ __forceinline__ unsigned long long ffma2(unsigned long long a,
                                                    unsigned long long b,
                                                    unsigned long long c) {
    unsigned long long d;
    asm("fma.rn.f32x2 %0, %1, %2, %3;" : "=l"(d) : "l"(a), "l"(b), "l"(c));
    return d;
}
__device__ __forceinline__ unsigned long long pack2(float lo, float hi) {
    unsigned long long d;
    asm("mov.b64 %0, {%1, %2};" : "=l"(d) : "f"(lo), "f"(hi));
    return d;
}
__device__ __forceinline__ float2 unpack2(unsigned long long v) {
    float2 r;
    asm("mov.b64 {%0, %1}, %2;" : "=f"(r.x), "=f"(r.y) : "l"(v));
    return r;
}
__device__ __forceinline__ float tanh_ap(float x) {
    float y;
    asm("tanh.approx.f32 %0, %1;" : "=f"(y) : "f"(x));
    return y;
}
__device__ __forceinline__ float sig_ap(float x) {
    return fmaf(tanh_ap(0.5f * x), 0.5f, 0.5f);
}

// A addressing: [b][k], row stride AROW, +4-word shift per batch-group of 8
// -> the 4 distinct lanes of an LDS.128 phase land on distinct granules.
__device__ __forceinline__ int aidx(int b, int k) {
    return b * AROW + ((b >> 3) << 2) + k;
}

// acc[g][ui][bi] over k-pairs.  C[32b x 512j] += A[32 x 128] * W[512 x 128]^T
__device__ __forceinline__ void gemm_step(const float* __restrict__ Wg,
                                          const float* __restrict__ A,
                                          float* __restrict__ sW,
                                          unsigned long long acc[4][2][8],
                                          int tid, int bg, int ug)
{
    const int ugx = ug & 7;
    const float* abase = A + bg * 8 * AROW + bg * 4;
    const int jstage = tid >> 3;
    const int gkstage = tid & 7;

#pragma unroll 1
    for (int ch = 0; ch < 4; ++ch) {
        __syncthreads();
        {
            const float4* src = (const float4*)(Wg + ch * 32 + gkstage * 4);
#pragma unroll
            for (int it = 0; it < 16; ++it) {
                int j = jstage + it * 32;
                float4 v = src[j * 32];            // Wg + j*128 + ch*32 + gk*4
                int gran = gkstage ^ ((j >> 1) & 7);
                *(float4*)(sW + j * 32 + gran * 4) = v;
            }
        }
        __syncthreads();

        const float* ab = abase + ch * 32;
#pragma unroll
        for (int k4 = 0; k4 < 8; ++k4) {
            const int gran = (k4 ^ ugx) << 2;
            unsigned long long w0[4][2], w1[4][2];
#pragma unroll
            for (int g = 0; g < 4; ++g)
#pragma unroll
                for (int ui = 0; ui < 2; ++ui) {
                    int j = g * H + ug * 2 + ui;
                    ulonglong2 wv = *(const ulonglong2*)(sW + j * 32 + gran);
                    w0[g][ui] = wv.x;
                    w1[g][ui] = wv.y;
                }
#pragma unroll
            for (int bi = 0; bi < 8; ++bi) {
                ulonglong2 av = *(const ulonglong2*)(ab + bi * AROW + k4 * 4);
#pragma unroll
                for (int g = 0; g < 4; ++g)
#pragma unroll
                    for (int ui = 0; ui < 2; ++ui) {
                        acc[g][ui][bi] = ffma2(w0[g][ui], av.x, acc[g][ui][bi]);
                        acc[g][ui][bi] = ffma2(w1[g][ui], av.y, acc[g][ui][bi]);
                    }
            }
        }
    }
}

__global__ void __launch_bounds__(NTHR, 1)
mcdrop_lstm_kernel(const float* __restrict__ obs,
                   const float* __restrict__ Wih0, const float* __restrict__ Whh0,
                   const float* __restrict__ bih0, const float* __restrict__ bhh0,
                   const float* __restrict__ Wih1, const float* __restrict__ Whh1,
                   const float* __restrict__ bih1, const float* __restrict__ bhh1,
                   const float* __restrict__ Wihc, const float* __restrict__ Whhc,
                   const float* __restrict__ bihc, const float* __restrict__ bhhc,
                   const float* __restrict__ Wout, const float* __restrict__ bout,
                   const float* __restrict__ encu, const float* __restrict__ hnu,
                   const float* __restrict__ decu, float* __restrict__ preds)
{
    extern __shared__ float smraw[];
    Smem* S = (Smem*)smraw;

    const int tid = threadIdx.x;
    const int bg  = tid & 3;      // 4 batch groups of 8
    const int ug  = tid >> 2;     // 64 unit groups of 2
    const int bglob0 = blockIdx.x * BT;

    for (int i = tid; i < G; i += NTHR) {
        S->B0[i] = bih0[i] + bhh0[i];
        S->B1[i] = bih1[i] + bhh1[i];
        S->BC[i] = bihc[i] + bhhc[i];
        S->Wih0[i * 2]     = Wih0[i * 2];
        S->Wih0[i * 2 + 1] = Wih0[i * 2 + 1];
        S->Wihc[i * 2]     = Wihc[i * 2];
        S->Wihc[i * 2 + 1] = Wihc[i * 2 + 1];
    }
    for (int i = tid; i < 2 * H; i += NTHR) S->Wout[i] = Wout[i];
    if (tid < 2) S->bout[tid] = bout[tid];
    for (int i = tid; i < ASZ; i += NTHR) {
        S->At0[i] = 0.0f; S->At1[i] = 0.0f; S->Dt[i] = 0.0f;
    }
    for (int i = tid; i < BT * H; i += NTHR) {
        S->Ct0[i] = 0.0f; S->Ct1[i] = 0.0f;
    }

    unsigned long long acc[4][2][8];

    // ===================== encoder =====================
#pragma unroll 1
    for (int t = 0; t < T_SEQ; ++t) {
        // ---- layer 0: acc = b0 + x_t @ Wih0^T (into lo lane) ----
        float2 xv[8];
#pragma unroll
        for (int bi = 0; bi < 8; ++bi)
            xv[bi] = *(const float2*)(obs + (size_t)(bglob0 + bg * 8 + bi) * (T_SEQ * 2) + t * 2);
#pragma unroll
        for (int g = 0; g < 4; ++g)
#pragma unroll
            for (int ui = 0; ui < 2; ++ui) {
                int j = g * H + ug * 2 + ui;
                float bb  = S->B0[j];
                float wi0 = S->Wih0[j * 2];
                float wi1 = S->Wih0[j * 2 + 1];
#pragma unroll
                for (int bi = 0; bi < 8; ++bi) {
                    float lo = fmaf(wi1, xv[bi].y, fmaf(wi0, xv[bi].x, bb));
                    acc[g][ui][bi] = pack2(lo, 0.0f);
                }
            }
        gemm_step(Whh0, S->At0, S->W, acc, tid, bg, ug);
        __syncthreads();   // everyone done reading At0 before we overwrite it

#pragma unroll
        for (int bi = 0; bi < 8; ++bi) {
            int b = bg * 8 + bi;
            int bgl = bglob0 + b;
            float2 uu = *(const float2*)(encu + ((size_t)t * B_TOT + bgl) * H + ug * 2);
#pragma unroll
            for (int ui = 0; ui < 2; ++ui) {
                int u = ug * 2 + ui;
                float2 pi = unpack2(acc[0][ui][bi]);
                float2 pf = unpack2(acc[1][ui][bi]);
                float2 pg = unpack2(acc[2][ui][bi]);
                float2 po = unpack2(acc[3][ui][bi]);
                float iv = sig_ap(pi.x + pi.y);
                float fv = sig_ap(pf.x + pf.y);
                float gv = tanh_ap(pg.x + pg.y);
                float ov = sig_ap(po.x + po.y);
                float c  = fmaf(fv, S->Ct0[b * H + u], iv * gv);
                S->Ct0[b * H + u] = c;
                float h  = ov * tanh_ap(c);
                float um = (ui == 0) ? uu.x : uu.y;
                S->At0[aidx(b, u)] = h;
                S->Dt [aidx(b, u)] = (um >= P_DROP) ? h * DROP_SCALE : 0.0f;
            }
        }

        // ---- layer 1 ----
#pragma unroll
        for (int g = 0; g < 4; ++g)
#pragma unroll
            for (int ui = 0; ui < 2; ++ui) {
                float bb = S->B1[g * H + ug * 2 + ui];
#pragma unroll
                for (int bi = 0; bi < 8; ++bi)
                    acc[g][ui][bi] = pack2(bb, 0.0f);
            }
        gemm_step(Wih1, S->Dt,  S->W, acc, tid, bg, ug);
        gemm_step(Whh1, S->At1, S->W, acc, tid, bg, ug);
        __syncthreads();

#pragma unroll
        for (int bi = 0; bi < 8; ++bi) {
            int b = bg * 8 + bi;
#pragma unroll
            for (int ui = 0; ui < 2; ++ui) {
                int u = ug * 2 + ui;
                float2 pi = unpack2(acc[0][ui][bi]);
                float2 pf = unpack2(acc[1][ui][bi]);
                float2 pg = unpack2(acc[2][ui][bi]);
                float2 po = unpack2(acc[3][ui][bi]);
                float iv = sig_ap(pi.x + pi.y);
                float fv = sig_ap(pf.x + pf.y);
                float gv = tanh_ap(pg.x + pg.y);
                float ov = sig_ap(po.x + po.y);
                float c  = fmaf(fv, S->Ct1[b * H + u], iv * gv);
                S->Ct1[b * H + u] = c;
                S->At1[aidx(b, u)] = ov * tanh_ap(c);
            }
        }
    }

    // ===================== decoder init =====================
#pragma unroll
    for (int bi = 0; bi < 8; ++bi) {
        int b = bg * 8 + bi;
        int bgl = bglob0 + b;
        float2 uu = *(const float2*)(hnu + (size_t)bgl * H + ug * 2);
#pragma unroll
        for (int ui = 0; ui < 2; ++ui) {
            int u = ug * 2 + ui;
            float h1v = S->At1[aidx(b, u)];   // own writes
            float um = (ui == 0) ? uu.x : uu.y;
            S->At0[aidx(b, u)] = (um >= P_DROP) ? h1v * DROP_SCALE : 0.0f;
        }
    }
    if (tid < BT * 2) {
        int b = tid >> 1, d = tid & 1;
        S->X[tid] = obs[(size_t)(bglob0 + b) * (T_SEQ * 2) + (size_t)(T_SEQ - 1) * 2 + d];
    }

    // ===================== decoder =====================
#pragma unroll 1
    for (int p = 0; p < PL; ++p) {
        __syncthreads();
        float2 xi[8];
#pragma unroll
        for (int bi = 0; bi < 8; ++bi)
            xi[bi] = *(const float2*)(&S->X[(bg * 8 + bi) * 2]);
#pragma unroll
        for (int g = 0; g < 4; ++g)
#pragma unroll
            for (int ui = 0; ui < 2; ++ui) {
                int j = g * H + ug * 2 + ui;
                float bb  = S->BC[j];
                float wi0 = S->Wihc[j * 2];
                float wi1 = S->Wihc[j * 2 + 1];
#pragma unroll
                for (int bi = 0; bi < 8; ++bi) {
                    float lo = fmaf(wi1, xi[bi].y, fmaf(wi0, xi[bi].x, bb));
                    acc[g][ui][bi] = pack2(lo, 0.0f);
                }
            }
        gemm_step(Whhc, S->At0, S->W, acc, tid, bg, ug);
        __syncthreads();

#pragma unroll
        for (int bi = 0; bi < 8; ++bi) {
            int b = bg * 8 + bi;
            int bgl = bglob0 + b;
            float2 uu = *(const float2*)(decu + ((size_t)p * B_TOT + bgl) * H + ug * 2);
#pragma unroll
            for (int ui = 0; ui < 2; ++ui) {
                int u = ug * 2 + ui;
                float2 pi = unpack2(acc[0][ui][bi]);
                float2 pf = unpack2(acc[1][ui][bi]);
                float2 pg = unpack2(acc[2][ui][bi]);
                float2 po = unpack2(acc[3][ui][bi]);
                float iv = sig_ap(pi.x + pi.y);
                float fv = sig_ap(pf.x + pf.y);
                float gv = tanh_ap(pg.x + pg.y);
                float ov = sig_ap(po.x + po.y);
                float c  = fmaf(fv, S->Ct1[b * H + u], iv * gv);
                S->Ct1[b * H + u] = c;
                float h  = ov * tanh_ap(c);
                float um = (ui == 0) ? uu.x : uu.y;
                S->At0[aidx(b, u)] = (um >= P_DROP) ? h * DROP_SCALE : 0.0f;
            }
        }
        __syncthreads();

        if (tid < BT * 2) {
            int b = tid >> 1, d = tid & 1;
            float s = S->bout[d];
            const float* wr = &S->Wout[d * H];
#pragma unroll 8
            for (int k = 0; k < H; ++k)
                s = fmaf(wr[k], S->At0[aidx(b, k)], s);
            S->X[b * 2 + d] = s;
            preds[((size_t)(bglob0 + b) * PL + p) * 2 + d] = s;
        }
    }
}

extern "C" void kernel_launch(void* const* d_in, const int* in_sizes, int n_in,
                              void* d_out, int out_size) {
    (void)in_sizes; (void)n_in; (void)out_size;
    const float* obs  = (const float*)d_in[0];
    const float* Wih0 = (const float*)d_in[1];
    const float* Whh0 = (const float*)d_in[2];
    const float* bih0 = (const float*)d_in[3];
    const float* bhh0 = (const float*)d_in[4];
    const float* Wih1 = (const float*)d_in[5];
    const float* Whh1 = (const float*)d_in[6];
    const float* bih1 = (const float*)d_in[7];
    const float* bhh1 = (const float*)d_in[8];
    const float* Wihc = (const float*)d_in[9];
    const float* Whhc = (const float*)d_in[10];
    const float* bihc = (const float*)d_in[11];
    const float* bhhc = (const float*)d_in[12];
    const float* Wout = (const float*)d_in[13];
    const float* bout = (const float*)d_in[14];
    const float* encu = (const float*)d_in[15];
    const float* hnu  = (const float*)d_in[16];
    const float* decu = (const float*)d_in[17];
    float* preds = (float*)d_out;

    int smem = (int)sizeof(Smem);
    cudaFuncSetAttribute(mcdrop_lstm_kernel,
                         cudaFuncAttributeMaxDynamicSharedMemorySize, smem);
    mcdrop_lstm_kernel<<<B_TOT / BT, NTHR, smem>>>(
        obs, Wih0, Whh0, bih0, bhh0, Wih1, Whh1, bih1, bhh1,
        Wihc, Whhc, bihc, bhhc, Wout, bout, encu, hnu, decu, preds);
}

// round 7
// speedup vs baseline: 1.0015x; 1.0015x over previous
#include <cuda_runtime.h>

#define NTHR  256
#define BT    32
#define H     128
#define G     512
#define T_SEQ 32
#define B_TOT 32768
#define PL    12
#define P_DROP 0.3f
#define DROP_SCALE (1.0f / 0.7f)

#define AROW  132                 // A row stride (words): 128 + 4 pad
#define ASZ   (BT * AROW + 16)    // + slack for the per-bg +4 offset
#define WSZ   (G * 32)            // 512 rows x 32 k-chunk, xor-swizzled granules

struct Smem {
    float At0[ASZ];     // h0 (and decoder h), [b][k] k-contiguous
    float At1[ASZ];     // h1
    float Dt [ASZ];     // dropped layer0 output
    float Ct0[BT * H];  // c state layer0
    float Ct1[BT * H];  // c state layer1 / decoder
    float W  [WSZ];     // staged weight chunk
    float B0 [G], B1 [G], BC [G];
    float Wih0[G * 2], Wihc[G * 2];
    float Wout[2 * H];
    float bout[2];
    float X  [BT * 2];
};

// ---- packed fp32x2 helpers (exact IEEE fma per lane) ----
__device__ __forceinline__ unsigned long long ffma2(unsigned long long a,
                                                    unsigned long long b,
                                                    unsigned long long c) {
    unsigned long long d;
    asm("fma.rn.f32x2 %0, %1, %2, %3;" : "=l"(d) : "l"(a), "l"(b), "l"(c));
    return d;
}
__device__ __forceinline__ unsigned long long pack2(float lo, float hi) {
    unsigned long long d;
    asm("mov.b64 %0, {%1, %2};" : "=l"(d) : "f"(lo), "f"(hi));
    return d;
}
__device__ __forceinline__ float2 unpack2(unsigned long long v) {
    float2 r;
    asm("mov.b64 {%0, %1}, %2;" : "=f"(r.x), "=f"(r.y) : "l"(v));
    return r;
}
__device__ __forceinline__ float tanh_ap(float x) {
    float y;
    asm("tanh.approx.f32 %0, %1;" : "=f"(y) : "f"(x));
    return y;
}
__device__ __forceinline__ float sig_ap(float x) {
    return fmaf(tanh_ap(0.5f * x), 0.5f, 0.5f);
}

// A addressing: [b][k], row stride AROW, +4-word shift per batch-group of 8
// -> the 4 distinct lanes of an LDS.128 phase land on distinct granules.
__device__ __forceinline__ int aidx(int b, int k) {
    return b * AROW + ((b >> 3) << 2) + k;
}

// acc[g][ui][bi] over k-pairs.  C[32b x 512j] += A[32 x 128] * W[512 x 128]^T
__device__ __forceinline__ void gemm_step(const float* __restrict__ Wg,
                                          const float* __restrict__ A,
                                          float* __restrict__ sW,
                                          unsigned long long acc[4][2][8],
                                          int tid, int bg, int ug)
{
    const int ugx = ug & 7;
    const float* abase = A + bg * 8 * AROW + bg * 4;
    const int jstage = tid >> 3;
    const int gkstage = tid & 7;

#pragma unroll 1
    for (int ch = 0; ch < 4; ++ch) {
        __syncthreads();
        {
            const float4* src = (const float4*)(Wg + ch * 32 + gkstage * 4);
#pragma unroll
            for (int it = 0; it < 16; ++it) {
                int j = jstage + it * 32;
                float4 v = src[j * 32];            // Wg + j*128 + ch*32 + gk*4
                int gran = gkstage ^ ((j >> 1) & 7);
                *(float4*)(sW + j * 32 + gran * 4) = v;
            }
        }
        __syncthreads();

        const float* ab = abase + ch * 32;
#pragma unroll
        for (int k4 = 0; k4 < 8; ++k4) {
            const int gran = (k4 ^ ugx) << 2;
            unsigned long long w0[4][2], w1[4][2];
#pragma unroll
            for (int g = 0; g < 4; ++g)
#pragma unroll
                for (int ui = 0; ui < 2; ++ui) {
                    int j = g * H + ug * 2 + ui;
                    ulonglong2 wv = *(const ulonglong2*)(sW + j * 32 + gran);
                    w0[g][ui] = wv.x;
                    w1[g][ui] = wv.y;
                }
#pragma unroll
            for (int bi = 0; bi < 8; ++bi) {
                ulonglong2 av = *(const ulonglong2*)(ab + bi * AROW + k4 * 4);
#pragma unroll
                for (int g = 0; g < 4; ++g)
#pragma unroll
                    for (int ui = 0; ui < 2; ++ui) {
                        acc[g][ui][bi] = ffma2(w0[g][ui], av.x, acc[g][ui][bi]);
                        acc[g][ui][bi] = ffma2(w1[g][ui], av.y, acc[g][ui][bi]);
                    }
            }
        }
    }
}

__global__ void __launch_bounds__(NTHR, 1)
mcdrop_lstm_kernel(const float* __restrict__ obs,
                   const float* __restrict__ Wih0, const float* __restrict__ Whh0,
                   const float* __restrict__ bih0, const float* __restrict__ bhh0,
                   const float* __restrict__ Wih1, const float* __restrict__ Whh1,
                   const float* __restrict__ bih1, const float* __restrict__ bhh1,
                   const float* __restrict__ Wihc, const float* __restrict__ Whhc,
                   const float* __restrict__ bihc, const float* __restrict__ bhhc,
                   const float* __restrict__ Wout, const float* __restrict__ bout,
                   const float* __restrict__ encu, const float* __restrict__ hnu,
                   const float* __restrict__ decu, float* __restrict__ preds)
{
    extern __shared__ float smraw[];
    Smem* S = (Smem*)smraw;

    const int tid = threadIdx.x;
    const int bg  = tid & 3;      // 4 batch groups of 8
    const int ug  = tid >> 2;     // 64 unit groups of 2
    const int bglob0 = blockIdx.x * BT;

    for (int i = tid; i < G; i += NTHR) {
        S->B0[i] = bih0[i] + bhh0[i];
        S->B1[i] = bih1[i] + bhh1[i];
        S->BC[i] = bihc[i] + bhhc[i];
        S->Wih0[i * 2]     = Wih0[i * 2];
        S->Wih0[i * 2 + 1] = Wih0[i * 2 + 1];
        S->Wihc[i * 2]     = Wihc[i * 2];
        S->Wihc[i * 2 + 1] = Wihc[i * 2 + 1];
    }
    for (int i = tid; i < 2 * H; i += NTHR) S->Wout[i] = Wout[i];
    if (tid < 2) S->bout[tid] = bout[tid];
    for (int i = tid; i < ASZ; i += NTHR) {
        S->At0[i] = 0.0f; S->At1[i] = 0.0f; S->Dt[i] = 0.0f;
    }
    for (int i = tid; i < BT * H; i += NTHR) {
        S->Ct0[i] = 0.0f; S->Ct1[i] = 0.0f;
    }

    unsigned long long acc[4][2][8];

    // ===================== encoder =====================
#pragma unroll 1
    for (int t = 0; t < T_SEQ; ++t) {
        // ---- layer 0: acc = b0 + x_t @ Wih0^T (into lo lane) ----
        float2 xv[8];
#pragma unroll
        for (int bi = 0; bi < 8; ++bi)
            xv[bi] = *(const float2*)(obs + (size_t)(bglob0 + bg * 8 + bi) * (T_SEQ * 2) + t * 2);
#pragma unroll
        for (int g = 0; g < 4; ++g)
#pragma unroll
            for (int ui = 0; ui < 2; ++ui) {
                int j = g * H + ug * 2 + ui;
                float bb  = S->B0[j];
                float wi0 = S->Wih0[j * 2];
                float wi1 = S->Wih0[j * 2 + 1];
#pragma unroll
                for (int bi = 0; bi < 8; ++bi) {
                    float lo = fmaf(wi1, xv[bi].y, fmaf(wi0, xv[bi].x, bb));
                    acc[g][ui][bi] = pack2(lo, 0.0f);
                }
            }
        gemm_step(Whh0, S->At0, S->W, acc, tid, bg, ug);
        __syncthreads();   // everyone done reading At0 before we overwrite it

#pragma unroll
        for (int bi = 0; bi < 8; ++bi) {
            int b = bg * 8 + bi;
            int bgl = bglob0 + b;
            float2 uu = *(const float2*)(encu + ((size_t)t * B_TOT + bgl) * H + ug * 2);
#pragma unroll
            for (int ui = 0; ui < 2; ++ui) {
                int u = ug * 2 + ui;
                float2 pi = unpack2(acc[0][ui][bi]);
                float2 pf = unpack2(acc[1][ui][bi]);
                float2 pg = unpack2(acc[2][ui][bi]);
                float2 po = unpack2(acc[3][ui][bi]);
                float iv = sig_ap(pi.x + pi.y);
                float fv = sig_ap(pf.x + pf.y);
                float gv = tanh_ap(pg.x + pg.y);
                float ov = sig_ap(po.x + po.y);
                float c  = fmaf(fv, S->Ct0[b * H + u], iv * gv);
                S->Ct0[b * H + u] = c;
                float h  = ov * tanh_ap(c);
                float um = (ui == 0) ? uu.x : uu.y;
                S->At0[aidx(b, u)] = h;
                S->Dt [aidx(b, u)] = (um >= P_DROP) ? h * DROP_SCALE : 0.0f;
            }
        }

        // ---- layer 1 ----
#pragma unroll
        for (int g = 0; g < 4; ++g)
#pragma unroll
            for (int ui = 0; ui < 2; ++ui) {
                float bb = S->B1[g * H + ug * 2 + ui];
#pragma unroll
                for (int bi = 0; bi < 8; ++bi)
                    acc[g][ui][bi] = pack2(bb, 0.0f);
            }
        gemm_step(Wih1, S->Dt,  S->W, acc, tid, bg, ug);
        gemm_step(Whh1, S->At1, S->W, acc, tid, bg, ug);
        __syncthreads();

#pragma unroll
        for (int bi = 0; bi < 8; ++bi) {
            int b = bg * 8 + bi;
#pragma unroll
            for (int ui = 0; ui < 2; ++ui) {
                int u = ug * 2 + ui;
                float2 pi = unpack2(acc[0][ui][bi]);
                float2 pf = unpack2(acc[1][ui][bi]);
                float2 pg = unpack2(acc[2][ui][bi]);
                float2 po = unpack2(acc[3][ui][bi]);
                float iv = sig_ap(pi.x + pi.y);
                float fv = sig_ap(pf.x + pf.y);
                float gv = tanh_ap(pg.x + pg.y);
                float ov = sig_ap(po.x + po.y);
                float c  = fmaf(fv, S->Ct1[b * H + u], iv * gv);
                S->Ct1[b * H + u] = c;
                S->At1[aidx(b, u)] = ov * tanh_ap(c);
            }
        }
    }

    // ===================== decoder init =====================
#pragma unroll
    for (int bi = 0; bi < 8; ++bi) {
        int b = bg * 8 + bi;
        int bgl = bglob0 + b;
        float2 uu = *(const float2*)(hnu + (size_t)bgl * H + ug * 2);
#pragma unroll
        for (int ui = 0; ui < 2; ++ui) {
            int u = ug * 2 + ui;
            float h1v = S->At1[aidx(b, u)];   // own writes
            float um = (ui == 0) ? uu.x : uu.y;
            S->At0[aidx(b, u)] = (um >= P_DROP) ? h1v * DROP_SCALE : 0.0f;
        }
    }
    if (tid < BT * 2) {
        int b = tid >> 1, d = tid & 1;
        S->X[tid] = obs[(size_t)(bglob0 + b) * (T_SEQ * 2) + (size_t)(T_SEQ - 1) * 2 + d];
    }

    // ===================== decoder =====================
#pragma unroll 1
    for (int p = 0; p < PL; ++p) {
        __syncthreads();
        float2 xi[8];
#pragma unroll
        for (int bi = 0; bi < 8; ++bi)
            xi[bi] = *(const float2*)(&S->X[(bg * 8 + bi) * 2]);
#pragma unroll
        for (int g = 0; g < 4; ++g)
#pragma unroll
            for (int ui = 0; ui < 2; ++ui) {
                int j = g * H + ug * 2 + ui;
                float bb  = S->BC[j];
                float wi0 = S->Wihc[j * 2];
                float wi1 = S->Wihc[j * 2 + 1];
#pragma unroll
                for (int bi = 0; bi < 8; ++bi) {
                    float lo = fmaf(wi1, xi[bi].y, fmaf(wi0, xi[bi].x, bb));
                    acc[g][ui][bi] = pack2(lo, 0.0f);
                }
            }
        gemm_step(Whhc, S->At0, S->W, acc, tid, bg, ug);
        __syncthreads();

#pragma unroll
        for (int bi = 0; bi < 8; ++bi) {
            int b = bg * 8 + bi;
            int bgl = bglob0 + b;
            float2 uu = *(const float2*)(decu + ((size_t)p * B_TOT + bgl) * H + ug * 2);
#pragma unroll
            for (int ui = 0; ui < 2; ++ui) {
                int u = ug * 2 + ui;
                float2 pi = unpack2(acc[0][ui][bi]);
                float2 pf = unpack2(acc[1][ui][bi]);
                float2 pg = unpack2(acc[2][ui][bi]);
                float2 po = unpack2(acc[3][ui][bi]);
                float iv = sig_ap(pi.x + pi.y);
                float fv = sig_ap(pf.x + pf.y);
                float gv = tanh_ap(pg.x + pg.y);
                float ov = sig_ap(po.x + po.y);
                float c  = fmaf(fv, S->Ct1[b * H + u], iv * gv);
                S->Ct1[b * H + u] = c;
                float h  = ov * tanh_ap(c);
                float um = (ui == 0) ? uu.x : uu.y;
                S->At0[aidx(b, u)] = (um >= P_DROP) ? h * DROP_SCALE : 0.0f;
            }
        }
        __syncthreads();

        if (tid < BT * 2) {
            int b = tid >> 1, d = tid & 1;
            float s = S->bout[d];
            const float* wr = &S->Wout[d * H];
#pragma unroll 8
            for (int k = 0; k < H; ++k)
                s = fmaf(wr[k], S->At0[aidx(b, k)], s);
            S->X[b * 2 + d] = s;
            preds[((size_t)(bglob0 + b) * PL + p) * 2 + d] = s;
        }
    }
}

extern "C" void kernel_launch(void* const* d_in, const int* in_sizes, int n_in,
                              void* d_out, int out_size) {
    (void)in_sizes; (void)n_in; (void)out_size;
    const float* obs  = (const float*)d_in[0];
    const float* Wih0 = (const float*)d_in[1];
    const float* Whh0 = (const float*)d_in[2];
    const float* bih0 = (const float*)d_in[3];
    const float* bhh0 = (const float*)d_in[4];
    const float* Wih1 = (const float*)d_in[5];
    const float* Whh1 = (const float*)d_in[6];
    const float* bih1 = (const float*)d_in[7];
    const float* bhh1 = (const float*)d_in[8];
    const float* Wihc = (const float*)d_in[9];
    const float* Whhc = (const float*)d_in[10];
    const float* bihc = (const float*)d_in[11];
    const float* bhhc = (const float*)d_in[12];
    const float* Wout = (const float*)d_in[13];
    const float* bout = (const float*)d_in[14];
    const float* encu = (const float*)d_in[15];
    const float* hnu  = (const float*)d_in[16];
    const float* decu = (const float*)d_in[17];
    float* preds = (float*)d_out;

    int smem = (int)sizeof(Smem);
    cudaFuncSetAttribute(mcdrop_lstm_kernel,
                         cudaFuncAttributeMaxDynamicSharedMemorySize, smem);
    mcdrop_lstm_kernel<<<B_TOT / BT, NTHR, smem>>>(
        obs, Wih0, Whh0, bih0, bhh0, Wih1, Whh1, bih1, bhh1,
        Wihc, Whhc, bihc, bhhc, Wout, bout, encu, hnu, decu, preds);
}

// round 13
// speedup vs baseline: 2.4244x; 2.4207x over previous
#include <cuda_runtime.h>
#include <cuda_bf16.h>
#include <cstdint>

#define NTHR 256
#define BM 64
#define B_TOT 32768
#define T_SEQ 32
#define PL 12
#define HD 128
#define P_DROP 0.3f
#define DSCALE (1.0f/0.7f)

#define SM_A0H 0
#define SM_A0L 16384
#define SM_A1H 32768
#define SM_A1L 49152
#define SM_M   65536
#define SM_C0  81920
#define SM_C1  114688
#define SM_W   147456
#define SM_B0  212992
#define SM_B1  215040
#define SM_BC  217088
#define SM_WI0 219136
#define SM_WIC 223232
#define SM_WO  227328
#define SM_X   228352
#define SM_BO  228864
#define SM_TOT 228872

// pre-split recurrent weights, smem image baked: [mat][chunk c][8192 bf16]
__device__ __nv_bfloat16 g_Wh[4 * 65536];
__device__ __nv_bfloat16 g_Wl[4 * 65536];

__device__ __forceinline__ void mma_bf(float (&d)[4], const uint32_t (&a)[4], const uint32_t (&b)[2]) {
    asm volatile("mma.sync.aligned.m16n8k16.row.col.f32.bf16.bf16.f32 "
        "{%0,%1,%2,%3}, {%4,%5,%6,%7}, {%8,%9}, {%0,%1,%2,%3};"
        : "+f"(d[0]), "+f"(d[1]), "+f"(d[2]), "+f"(d[3])
        : "r"(a[0]), "r"(a[1]), "r"(a[2]), "r"(a[3]), "r"(b[0]), "r"(b[1]));
}
__device__ __forceinline__ void cpa(uint32_t s, const void* g) {
    asm volatile("cp.async.cg.shared.global [%0], [%1], 16;" :: "r"(s), "l"(g));
}
#define CP_COMMIT() asm volatile("cp.async.commit_group;" ::: "memory")
#define CP_WAIT1()  asm volatile("cp.async.wait_group 1;" ::: "memory")
#define CP_WAIT0()  asm volatile("cp.async.wait_group 0;" ::: "memory")

__device__ __forceinline__ uint32_t smem_u32(const void* p) {
    uint32_t a;
    asm("{ .reg .u64 t; cvta.to.shared.u64 t, %1; cvt.u32.u64 %0, t; }" : "=r"(a) : "l"(p));
    return a;
}
__device__ __forceinline__ float tanh_ap(float x) {
    float y; asm("tanh.approx.f32 %0, %1;" : "=f"(y) : "f"(x)); return y;
}
__device__ __forceinline__ float sigf(float x) { return fmaf(tanh_ap(0.5f * x), 0.5f, 0.5f); }

__device__ __forceinline__ void split2(float a, float b, uint32_t& hi, uint32_t& lo) {
    __nv_bfloat162 h2 = __floats2bfloat162_rn(a, b);
    float2 hf = __bfloat1622float2(h2);
    __nv_bfloat162 l2 = __floats2bfloat162_rn(a - hf.x, b - hf.y);
    hi = *(uint32_t*)&h2; lo = *(uint32_t*)&l2;
}
// A tile [64r x 128k] bf16: row 256B (16 granules); swizzle XORs the LOW 3
// granule bits with r&7; granule bit 3 (k>>6) is preserved.  (R12 bug: bit
// 7 was dropped -> k>=64 aliased onto k<64.)
__device__ __forceinline__ uint32_t a_off(int r, int k) {
    return (uint32_t)(r * 256 + ((k >> 6) << 7)
                      + ((((k >> 3) & 7) ^ (r & 7)) << 4) + ((k & 7) << 1));
}
// W chunk [512j x 16k] bf16: row 32B, 2 granules xor (j>>2)&1  (injective)
__device__ __forceinline__ uint32_t w_off(int j, int kc) {
    return (uint32_t)(j * 32 + ((((kc >> 3) & 1) ^ ((j >> 2) & 1)) << 4) + ((kc & 7) << 1));
}

__global__ void prep_kernel(const float* __restrict__ W0, const float* __restrict__ W1i,
                            const float* __restrict__ W1h, const float* __restrict__ Wc) {
    int idx = blockIdx.x * blockDim.x + threadIdx.x;
    for (int e = idx; e < 4 * 65536; e += 65536) {
        int m = e >> 16, r = e & 65535;
        int j = r >> 7, k = r & 127;
        const float* s = (m == 0) ? W0 : (m == 1) ? W1i : (m == 2) ? W1h : Wc;
        float v = s[r];
        if (m == 1) v *= DSCALE;
        __nv_bfloat16 hi = __float2bfloat16(v);
        __nv_bfloat16 lo = __float2bfloat16(v - __bfloat162float(hi));
        int c = k >> 4, kc = k & 15;
        int off = j * 16 + ((((kc >> 3) & 1) ^ ((j >> 2) & 1)) << 3) + (kc & 7);
        g_Wh[m * 65536 + c * 8192 + off] = hi;
        g_Wl[m * 65536 + c * 8192 + off] = lo;
    }
}

__device__ __forceinline__ void cp_chunk(uint32_t dst, const __nv_bfloat16* gh,
                                         const __nv_bfloat16* gl, int tid) {
#pragma unroll
    for (int q = 0; q < 4; ++q) {
        uint32_t o = (uint32_t)(tid * 16 + q * 4096);
        cpa(dst + o, (const char*)gh + o);
        cpa(dst + 16384 + o, (const char*)gl + o);
    }
}

// Direct per-thread fragment loads at documented m16n8k16 coordinates:
//  A regs: [0]=(r=gid, k0) [1]=(r+8, k0) [2]=(r, k0+8) [3]=(r+8, k0+8), pair at k,k+1
//  B regs: [0]=(j=j0+gid, k=2*tig) [1]=(j, k=8+2*tig)
//  D regs: [0,1]=(r=gid, n=2*tig,+1) [2,3]=(r+8, same n)
template<bool MASK>
__device__ __forceinline__ void mma_chunk(char* sm, int aH, int aL, uint32_t wb,
                                          int c, float (&acc)[2][16][4], int lane, int wm, int wj) {
    const int gid = lane >> 2, tig = lane & 3;
    const int k0 = c * 16 + tig * 2;
    uint32_t ah[2][4], al[2][4];
#pragma unroll
    for (int mt = 0; mt < 2; ++mt) {
        const int r0 = wm * 32 + mt * 16 + gid;
        uint32_t o[4];
        o[0] = a_off(r0, k0);
        o[1] = a_off(r0 + 8, k0);
        o[2] = a_off(r0, k0 + 8);
        o[3] = a_off(r0 + 8, k0 + 8);
#pragma unroll
        for (int i = 0; i < 4; ++i) {
            uint32_t h = *(const uint32_t*)(sm + aH + o[i]);
            uint32_t l = *(const uint32_t*)(sm + aL + o[i]);
            if (MASK) {
                uint32_t m = *(const uint32_t*)(sm + SM_M + o[i]);
                h &= m; l &= m;
            }
            ah[mt][i] = h; al[mt][i] = l;
        }
    }
#pragma unroll
    for (int nt = 0; nt < 16; ++nt) {
        const int g = nt >> 2, p = nt & 3;
        const int j = g * 128 + wj * 32 + p * 8 + gid;
        const uint32_t w0 = w_off(j, tig * 2), w1 = w_off(j, 8 + tig * 2);
        uint32_t bh[2], bl[2];
        bh[0] = *(const uint32_t*)(sm + wb + w0);
        bh[1] = *(const uint32_t*)(sm + wb + w1);
        bl[0] = *(const uint32_t*)(sm + wb + 16384 + w0);
        bl[1] = *(const uint32_t*)(sm + wb + 16384 + w1);
#pragma unroll
        for (int mt = 0; mt < 2; ++mt) {
            mma_bf(acc[mt][nt], ah[mt], bh);
            mma_bf(acc[mt][nt], ah[mt], bl);
            mma_bf(acc[mt][nt], al[mt], bh);
        }
    }
}

template<bool MASK>
__device__ __forceinline__ void gemm(char* sm, uint32_t smb, int mat, int aH, int aL,
                                     float (&acc)[2][16][4], int tid, int lane, int wm, int wj) {
    const __nv_bfloat16* gh = g_Wh + mat * 65536;
    const __nv_bfloat16* gl = g_Wl + mat * 65536;
    cp_chunk(smb + SM_W, gh, gl, tid);
    CP_COMMIT();
#pragma unroll 1
    for (int c = 0; c < 8; ++c) {
        if (c < 7) {
            cp_chunk(smb + SM_W + (uint32_t)(((c + 1) & 1) * 32768), gh + (c + 1) * 8192, gl + (c + 1) * 8192, tid);
            CP_COMMIT();
            CP_WAIT1();
        } else CP_WAIT0();
        __syncthreads();
        mma_chunk<MASK>(sm, aH, aL, (uint32_t)(SM_W + (c & 1) * 32768), c, acc, lane, wm, wj);
        __syncthreads();
    }
}

__device__ __forceinline__ void zacc(float (&a)[2][16][4]) {
#pragma unroll
    for (int i = 0; i < 2; ++i)
#pragma unroll
        for (int j = 0; j < 16; ++j)
#pragma unroll
            for (int q = 0; q < 4; ++q) a[i][j][q] = 0.f;
}

// E=0: enc L0 (x from obs; writes A0 + mask M; c=C0)
// E=1: enc L1 (writes A1; c=C1)
// E=2: decoder (x from SM_X; writes dropped h to A0; c=C1)
template<int E>
__device__ __forceinline__ void epilogue(char* sm, float (&acc)[2][16][4], int lane, int wm, int wj,
                                         size_t bg0, const float* __restrict__ obs, int t,
                                         const float* __restrict__ mbase) {
    const int boff = (E == 0) ? SM_B0 : (E == 1) ? SM_B1 : SM_BC;
    const int wxoff = (E == 0) ? SM_WI0 : SM_WIC;
    const int coff = (E == 0) ? SM_C0 : SM_C1;
    const int aoH = (E == 1) ? SM_A1H : SM_A0H;
    const int aoL = (E == 1) ? SM_A1L : SM_A0L;
#pragma unroll
    for (int mt = 0; mt < 2; ++mt)
#pragma unroll
    for (int rh = 0; rh < 2; ++rh) {
        const int b = wm * 32 + mt * 16 + rh * 8 + (lane >> 2);
        float x0 = 0.f, x1 = 0.f;
        if (E == 0) {
            float2 xv = *(const float2*)(obs + (bg0 + b) * (T_SEQ * 2) + t * 2);
            x0 = xv.x; x1 = xv.y;
        }
        if (E == 2) {
            const float* X = (const float*)(sm + SM_X);
            x0 = X[b * 2]; x1 = X[b * 2 + 1];
        }
        const float* mrow = (E != 1) ? (mbase + (bg0 + b) * HD) : (const float*)0;
#pragma unroll
        for (int p = 0; p < 4; ++p) {
            const int u = wj * 32 + p * 8 + (lane & 3) * 2;
            float2 mk = make_float2(1.f, 1.f);
            if (E != 1) mk = *(const float2*)(mrow + u);
            float ga[4][2];
#pragma unroll
            for (int g = 0; g < 4; ++g) {
                const int j = g * 128 + u;
                float2 bs = *(const float2*)(sm + boff + j * 4);
                float a0 = acc[mt][g * 4 + p][rh * 2 + 0] + bs.x;
                float a1 = acc[mt][g * 4 + p][rh * 2 + 1] + bs.y;
                if (E != 1) {
                    float4 w = *(const float4*)(sm + wxoff + j * 8);
                    a0 += x0 * w.x + x1 * w.y;
                    a1 += x0 * w.z + x1 * w.w;
                }
                ga[g][0] = a0; ga[g][1] = a1;
            }
            float2* cp2 = (float2*)(sm + coff + (b * 128 + u) * 4);
            float2 cc = *cp2;
            float hp[2];
#pragma unroll
            for (int q = 0; q < 2; ++q) {
                float iv = sigf(ga[0][q]), fv = sigf(ga[1][q]);
                float gv = tanh_ap(ga[2][q]), ov = sigf(ga[3][q]);
                float cn = fmaf(fv, q ? cc.y : cc.x, iv * gv);
                if (q) cc.y = cn; else cc.x = cn;
                hp[q] = ov * tanh_ap(cn);
            }
            *cp2 = cc;
            if (E == 2) {
                hp[0] = (mk.x >= P_DROP) ? hp[0] * DSCALE : 0.f;
                hp[1] = (mk.y >= P_DROP) ? hp[1] * DSCALE : 0.f;
            }
            uint32_t hi, lo;
            split2(hp[0], hp[1], hi, lo);
            const uint32_t ao = a_off(b, u);
            *(uint32_t*)(sm + aoH + ao) = hi;
            *(uint32_t*)(sm + aoL + ao) = lo;
            if (E == 0)
                *(uint32_t*)(sm + SM_M + ao) = ((mk.x >= P_DROP) ? 0x0000FFFFu : 0u)
                                             | ((mk.y >= P_DROP) ? 0xFFFF0000u : 0u);
        }
    }
}

__global__ void __launch_bounds__(NTHR, 1)
mcd_main(const float* __restrict__ obs,
         const float* __restrict__ bih0, const float* __restrict__ bhh0,
         const float* __restrict__ bih1, const float* __restrict__ bhh1,
         const float* __restrict__ bihc, const float* __restrict__ bhhc,
         const float* __restrict__ Wih0, const float* __restrict__ Wihc,
         const float* __restrict__ Wout, const float* __restrict__ bout,
         const float* __restrict__ encu, const float* __restrict__ hnu,
         const float* __restrict__ decu, float* __restrict__ preds)
{
    extern __shared__ char sm[];
    const uint32_t smb = smem_u32(sm);
    const int tid = threadIdx.x;
    const int w = tid >> 5, lane = tid & 31;
    const int wm = w & 1, wj = w >> 1;
    const size_t bg0 = (size_t)blockIdx.x * BM;

    for (int i = tid; i < 512; i += NTHR) {
        ((float*)(sm + SM_B0))[i] = bih0[i] + bhh0[i];
        ((float*)(sm + SM_B1))[i] = bih1[i] + bhh1[i];
        ((float*)(sm + SM_BC))[i] = bihc[i] + bhhc[i];
        ((float2*)(sm + SM_WI0))[i] = ((const float2*)Wih0)[i];
        ((float2*)(sm + SM_WIC))[i] = ((const float2*)Wihc)[i];
    }
    for (int i = tid; i < 256; i += NTHR) ((float*)(sm + SM_WO))[i] = Wout[i];
    if (tid < 2) ((float*)(sm + SM_BO))[tid] = bout[tid];
    for (int i = tid; i < 147456 / 16; i += NTHR) ((uint4*)sm)[i] = make_uint4(0, 0, 0, 0);
    __syncthreads();

    float acc[2][16][4];

    // ===== encoder =====
#pragma unroll 1
    for (int t = 0; t < T_SEQ; ++t) {
        zacc(acc);
        gemm<false>(sm, smb, 0, SM_A0H, SM_A0L, acc, tid, lane, wm, wj);
        epilogue<0>(sm, acc, lane, wm, wj, bg0, obs, t, encu + (size_t)t * B_TOT * HD);
        zacc(acc);
        gemm<true >(sm, smb, 1, SM_A0H, SM_A0L, acc, tid, lane, wm, wj);
        gemm<false>(sm, smb, 2, SM_A1H, SM_A1L, acc, tid, lane, wm, wj);
        epilogue<1>(sm, acc, lane, wm, wj, bg0, (const float*)0, 0, (const float*)0);
    }

    // ===== decoder init: A0 = split(drop(h1, hnu)); X = obs[:, T-1, :] =====
#pragma unroll
    for (int mt = 0; mt < 2; ++mt)
#pragma unroll
    for (int rh = 0; rh < 2; ++rh) {
        const int b = wm * 32 + mt * 16 + rh * 8 + (lane >> 2);
        const float* mrow = hnu + (bg0 + b) * HD;
#pragma unroll
        for (int p = 0; p < 4; ++p) {
            const int u = wj * 32 + p * 8 + (lane & 3) * 2;
            const uint32_t ao = a_off(b, u);
            uint32_t hi = *(uint32_t*)(sm + SM_A1H + ao);
            uint32_t lo = *(uint32_t*)(sm + SM_A1L + ao);
            float2 hf = __bfloat1622float2(*(__nv_bfloat162*)&hi);
            float2 lf = __bfloat1622float2(*(__nv_bfloat162*)&lo);
            float2 mk = *(const float2*)(mrow + u);
            float h0 = (mk.x >= P_DROP) ? (hf.x + lf.x) * DSCALE : 0.f;
            float h1 = (mk.y >= P_DROP) ? (hf.y + lf.y) * DSCALE : 0.f;
            split2(h0, h1, hi, lo);
            *(uint32_t*)(sm + SM_A0H + ao) = hi;
            *(uint32_t*)(sm + SM_A0L + ao) = lo;
        }
    }
    if (tid < BM * 2) {
        int b2 = tid >> 1, d = tid & 1;
        ((float*)(sm + SM_X))[tid] = obs[(bg0 + b2) * (T_SEQ * 2) + (T_SEQ - 1) * 2 + d];
    }

    // ===== decoder =====
#pragma unroll 1
    for (int p = 0; p < PL; ++p) {
        zacc(acc);
        gemm<false>(sm, smb, 3, SM_A0H, SM_A0L, acc, tid, lane, wm, wj);
        epilogue<2>(sm, acc, lane, wm, wj, bg0, (const float*)0, 0, decu + (size_t)p * B_TOT * HD);
        __syncthreads();
        if (tid < BM * 2) {
            int b2 = tid >> 1, d = tid & 1;
            float s = ((float*)(sm + SM_BO))[d];
            const float* wr = (float*)(sm + SM_WO) + d * 128;
#pragma unroll 4
            for (int k = 0; k < 128; k += 8) {
                uint32_t ao = a_off(b2, k);
                uint4 vh = *(uint4*)(sm + SM_A0H + ao);
                uint4 vl = *(uint4*)(sm + SM_A0L + ao);
                const uint32_t* p4 = &vh.x;
                const uint32_t* q4 = &vl.x;
#pragma unroll
                for (int q = 0; q < 4; ++q) {
                    float2 hf = __bfloat1622float2(*(__nv_bfloat162*)&p4[q]);
                    float2 lf = __bfloat1622float2(*(__nv_bfloat162*)&q4[q]);
                    s = fmaf(wr[k + q * 2],     hf.x + lf.x, s);
                    s = fmaf(wr[k + q * 2 + 1], hf.y + lf.y, s);
                }
            }
            ((float*)(sm + SM_X))[b2 * 2 + d] = s;
            preds[((bg0 + b2) * PL + p) * 2 + d] = s;
        }
        __syncthreads();
    }
}

extern "C" void kernel_launch(void* const* d_in, const int* in_sizes, int n_in,
                              void* d_out, int out_size) {
    (void)in_sizes; (void)n_in; (void)out_size;
    const float* obs  = (const float*)d_in[0];
    const float* Wih0 = (const float*)d_in[1];
    const float* Whh0 = (const float*)d_in[2];
    const float* bih0 = (const float*)d_in[3];
    const float* bhh0 = (const float*)d_in[4];
    const float* Wih1 = (const float*)d_in[5];
    const float* Whh1 = (const float*)d_in[6];
    const float* bih1 = (const float*)d_in[7];
    const float* bhh1 = (const float*)d_in[8];
    const float* Wihc = (const float*)d_in[9];
    const float* Whhc = (const float*)d_in[10];
    const float* bihc = (const float*)d_in[11];
    const float* bhhc = (const float*)d_in[12];
    const float* Wout = (const float*)d_in[13];
    const float* bout = (const float*)d_in[14];
    const float* encu = (const float*)d_in[15];
    const float* hnu  = (const float*)d_in[16];
    const float* decu = (const float*)d_in[17];
    float* preds = (float*)d_out;

    prep_kernel<<<256, 256>>>(Whh0, Wih1, Whh1, Whhc);
    cudaFuncSetAttribute(mcd_main, cudaFuncAttributeMaxDynamicSharedMemorySize, SM_TOT);
    mcd_main<<<B_TOT / BM, NTHR, SM_TOT>>>(
        obs, bih0, bhh0, bih1, bhh1, bihc, bhhc, Wih0, Wihc,
        Wout, bout, encu, hnu, decu, preds);
}